// round 2
// baseline (speedup 1.0000x reference)
#include <cuda_runtime.h>

#define Bn 16
#define Nn 1024
#define Dn 8
#define Cn 128
#define Hn 256
#define NCOND 3
#define MAXIT 4
#define NROWS (Bn * Nn)

// ---------------- device scratch (no allocations allowed) ----------------
__device__ __align__(16) float g_x0[Bn * Nn * Dn];      // 512 KB
__device__ float g_cc[Bn * Hn];
__device__ unsigned char g_mask[NROWS];
__device__ int g_cnt[MAXIT + 1];     // mask popcount after mismatch pass k
__device__ int g_nslot[MAXIT];       // list build slots per iteration
__device__ int g_list[NROWS];        // compacted masked-row indices (rebuilt per iter)
__device__ float g_partial[128];

// ---------------- init: x0 = where(cond, data, x0_noise); zero counters --
__global__ void k_init(const float* __restrict__ data,
                       const float* __restrict__ x0_noise) {
    int i = blockIdx.x * blockDim.x + threadIdx.x;
    if (i <= MAXIT) g_cnt[i] = 0;
    if (i < MAXIT) g_nslot[i] = 0;
    if (i < Bn * Nn * Dn) {
        int d = i & (Dn - 1);
        g_x0[i] = (d < NCOND) ? data[i] : x0_noise[i];
    }
}

// ---------------- cc = c @ Wc  (B x H) -----------------------------------
__global__ void k_cc(const float* __restrict__ c, const float* __restrict__ Wc) {
    int b = blockIdx.x;
    int h = threadIdx.x;
    float acc = 0.f;
    #pragma unroll 8
    for (int j = 0; j < Cn; j++)
        acc = fmaf(c[b * Cn + j], Wc[j * Hn + h], acc);
    g_cc[b * Hn + h] = acc;
}

// ---------------- full mismatch (iteration 0, all rows) -------------------
// grid = B*32 blocks, 128 threads; 32 rows/block, 4-way m-split per row.
// smem index for row m, half h:  2*m + (m>>8) + h   (pad -> conflict-free)
__global__ void k_mismatch_full(const float* __restrict__ data) {
    __shared__ float4 sdata[Nn * 2 + 4];
    __shared__ int sflag[32];

    const int tid  = threadIdx.x;
    const int b    = blockIdx.x >> 5;
    const int tile = blockIdx.x & 31;
    const int q    = tid & 3;          // m-quarter
    const int r    = tid >> 2;         // row within tile
    const int row  = tile * 32 + r;    // row within batch b

    const float4* dptr = (const float4*)(data + (size_t)b * Nn * Dn);
    for (int i = tid; i < Nn * 2; i += 128) {
        int m = i >> 1;
        sdata[i + (m >> 8)] = dptr[i];
    }
    __syncthreads();

    const float4* xr = (const float4*)(g_x0 + ((size_t)b * Nn + row) * Dn);
    const float4 xa = xr[0];
    const float4 xb = xr[1];

    float best = 3.402823466e38f;
    int bidx = -1;
    const int m0 = q * 256;
    #pragma unroll 4
    for (int m = m0; m < m0 + 256; m++) {
        int idx = 2 * m + q;
        float4 da = sdata[idx];
        float4 db = sdata[idx + 1];
        // sequential accumulation d = 0..7 (matches reference reduction order)
        float t0 = xa.x - da.x; float acc = t0 * t0;
        t0 = xa.y - da.y; acc = fmaf(t0, t0, acc);
        t0 = xa.z - da.z; acc = fmaf(t0, t0, acc);
        t0 = xa.w - da.w; acc = fmaf(t0, t0, acc);
        t0 = xb.x - db.x; acc = fmaf(t0, t0, acc);
        t0 = xb.y - db.y; acc = fmaf(t0, t0, acc);
        t0 = xb.z - db.z; acc = fmaf(t0, t0, acc);
        t0 = xb.w - db.w; acc = fmaf(t0, t0, acc);
        if (acc < best) { best = acc; bidx = m; }   // strict < -> first index
    }

    // merge the 4 m-quarters (lanes 4r..4r+3); tie -> lower m (first index)
    #pragma unroll
    for (int off = 2; off >= 1; off >>= 1) {
        float ob = __shfl_down_sync(0xffffffffu, best, off, 4);
        int   oi = __shfl_down_sync(0xffffffffu, bidx, off, 4);
        if (ob < best || (ob == best && oi < bidx)) { best = ob; bidx = oi; }
    }

    if (q == 0) {
        int mm = (bidx != row) ? 1 : 0;
        g_mask[b * Nn + row] = (unsigned char)mm;
        sflag[r] = mm;
    }
    __syncthreads();
    if (tid == 0) {
        int s = 0;
        #pragma unroll
        for (int i = 0; i < 32; i++) s += sflag[i];
        if (s) atomicAdd(&g_cnt[0], s);
    }
}

// ---------------- body: masked rows get fresh noise + build compact list --
__global__ void k_replace(const float* __restrict__ noise_bank, int iter) {
    if (g_cnt[iter] < 10) return;            // while-loop condition
    int i = blockIdx.x * blockDim.x + threadIdx.x;   // (b,n) flat
    if (i >= NROWS) return;
    if (g_mask[i]) {
        int slot = atomicAdd(&g_nslot[iter], 1);
        g_list[slot] = i;
        const float* nb = noise_bank + (size_t)iter * Bn * Nn * Dn + (size_t)i * Dn;
        float* x = g_x0 + (size_t)i * Dn;
        #pragma unroll
        for (int d = NCOND; d < Dn; d++) x[d] = nb[d];
    }
}

// ---------------- sparse mismatch: recompute only previously-masked rows --
// Unmasked rows are invariant (x and data unchanged => argmin unchanged).
// One row per warp; lanes split m by 32.
__global__ void k_mismatch_sparse(const float* __restrict__ data, int iter) {
    const int cnt = g_cnt[iter];
    if (cnt < 10) return;
    const int lane = threadIdx.x & 31;
    const int warp = (blockIdx.x * blockDim.x + threadIdx.x) >> 5;
    const int nwarps = (gridDim.x * blockDim.x) >> 5;

    for (int w = warp; w < cnt; w += nwarps) {
        const int rowflat = g_list[w];
        const int b = rowflat >> 10;
        const int n = rowflat & (Nn - 1);

        const float4* xr = (const float4*)(g_x0 + (size_t)rowflat * Dn);
        const float4 xa = xr[0];
        const float4 xb = xr[1];
        const float4* dp = (const float4*)(data + (size_t)b * Nn * Dn);

        float best = 3.402823466e38f;
        int bidx = -1;
        #pragma unroll 4
        for (int m = lane; m < Nn; m += 32) {
            float4 da = dp[2 * m];
            float4 db = dp[2 * m + 1];
            float t0 = xa.x - da.x; float acc = t0 * t0;
            t0 = xa.y - da.y; acc = fmaf(t0, t0, acc);
            t0 = xa.z - da.z; acc = fmaf(t0, t0, acc);
            t0 = xa.w - da.w; acc = fmaf(t0, t0, acc);
            t0 = xb.x - db.x; acc = fmaf(t0, t0, acc);
            t0 = xb.y - db.y; acc = fmaf(t0, t0, acc);
            t0 = xb.z - db.z; acc = fmaf(t0, t0, acc);
            t0 = xb.w - db.w; acc = fmaf(t0, t0, acc);
            if (acc < best) { best = acc; bidx = m; }
        }
        // warp argmin; tie -> lower m (first index)
        #pragma unroll
        for (int off = 16; off >= 1; off >>= 1) {
            float ob = __shfl_down_sync(0xffffffffu, best, off);
            int   oi = __shfl_down_sync(0xffffffffu, bidx, off);
            if (ob < best || (ob == best && oi < bidx)) { best = ob; bidx = oi; }
        }
        if (lane == 0) {
            int mm = (bidx != n) ? 1 : 0;
            g_mask[rowflat] = (unsigned char)mm;
            if (mm) atomicAdd(&g_cnt[iter + 1], 1);
        }
    }
}

// ---------------- fused model + masked squared-error partial sums ---------
// grid = 128 blocks (b*8 + tile), 128 threads, one row per thread.
__global__ void k_final(const float* __restrict__ data, const float* __restrict__ t,
                        const float* __restrict__ W1, const float* __restrict__ Wt,
                        const float* __restrict__ b1, const float* __restrict__ W2) {
    __shared__ float sW1[Dn * Hn];   // 8 KB  (D,H) row-major
    __shared__ float sW2[Hn * Dn];   // 8 KB  (H,D) row-major
    __shared__ float sbase[Hn];
    __shared__ float sred[128];

    const int bid  = blockIdx.x;
    const int b    = bid >> 3;
    const int tile = bid & 7;
    const int tid  = threadIdx.x;

    for (int i = tid; i < Dn * Hn; i += 128) sW1[i] = W1[i];
    for (int i = tid; i < Hn * Dn; i += 128) sW2[i] = W2[i];
    const float tb = t[b];
    for (int h = tid; h < Hn; h += 128)
        sbase[h] = g_cc[b * Hn + h] + tb * Wt[h] + b1[h];
    __syncthreads();

    const int row  = tile * 128 + tid;
    const int base = (b * Nn + row) * Dn;

    float xt[Dn], ut[Dn], vt[Dn];
    #pragma unroll
    for (int d = 0; d < Dn; d++) {
        float dv = data[base + d];
        float xv = g_x0[base + d];
        ut[d] = dv - xv;
        xt[d] = (d < NCOND) ? dv : ((1.0f - tb) * xv + tb * dv);
        vt[d] = 0.f;
    }

    for (int h = 0; h < Hn; h++) {
        float pre = sbase[h];
        #pragma unroll
        for (int d = 0; d < Dn; d++) pre = fmaf(xt[d], sW1[d * Hn + h], pre);
        float hh = tanhf(pre);
        #pragma unroll
        for (int d = 0; d < Dn; d++) vt[d] = fmaf(hh, sW2[h * Dn + d], vt[d]);
    }

    float part = 0.f;
    #pragma unroll
    for (int d = NCOND; d < Dn; d++) {
        float e = vt[d] - ut[d];
        part = fmaf(e, e, part);
    }

    sred[tid] = part;
    __syncthreads();
    for (int s = 64; s > 0; s >>= 1) {
        if (tid < s) sred[tid] += sred[tid + s];
        __syncthreads();
    }
    if (tid == 0) g_partial[bid] = sred[0];
}

// ---------------- final deterministic per-batch sum -----------------------
__global__ void k_finish(float* __restrict__ out) {
    int b = threadIdx.x;
    if (b < Bn) {
        float s = 0.f;
        #pragma unroll
        for (int i = 0; i < 8; i++) s += g_partial[b * 8 + i];
        out[b] = s / (float)(Nn * (Dn - NCOND));
    }
}

// ---------------- launch (graph-capturable, allocation-free) --------------
extern "C" void kernel_launch(void* const* d_in, const int* in_sizes, int n_in,
                              void* d_out, int out_size) {
    const float* data = (const float*)d_in[0];
    const float* c    = (const float*)d_in[1];
    const float* t    = (const float*)d_in[2];
    const float* x0n  = (const float*)d_in[3];
    const float* nb   = (const float*)d_in[4];
    const float* W1   = (const float*)d_in[5];
    const float* Wc   = (const float*)d_in[6];
    const float* Wt   = (const float*)d_in[7];
    const float* b1   = (const float*)d_in[8];
    const float* W2   = (const float*)d_in[9];
    float* out = (float*)d_out;

    k_init<<<(Bn * Nn * Dn + 255) / 256, 256>>>(data, x0n);
    k_cc<<<Bn, Hn>>>(c, Wc);
    k_mismatch_full<<<Bn * 32, 128>>>(data);
    for (int it = 0; it < MAXIT; it++) {
        k_replace<<<(NROWS + 255) / 256, 256>>>(nb, it);
        k_mismatch_sparse<<<128, 128>>>(data, it);
    }
    k_final<<<128, 128>>>(data, t, W1, Wt, b1, W2);
    k_finish<<<1, 32>>>(out);
}

// round 5
// speedup vs baseline: 1.7815x; 1.7815x over previous
#include <cuda_runtime.h>

#define Bn 16
#define Nn 1024
#define Dn 8
#define Cn 128
#define Hn 256
#define NCOND 3
#define MAXIT 4
#define NROWS (Bn * Nn)
#define GRID 128
#define TPB 512

// ---------------- device scratch (no allocations allowed) ----------------
__device__ __align__(16) float g_x0[NROWS * Dn];   // 512 KB
__device__ float g_cc[Bn * Hn];
__device__ int g_cnt[MAXIT + 1];                   // masked-row count after pass k
__device__ int g_lists[2][NROWS];                  // ping-pong compacted masked rows
__device__ float g_partial[GRID];
__device__ unsigned int g_barc[8];                 // monotonic barrier counters (never reset)

// Software grid barrier. Safe: GRID=128 blocks <= 148 SMs at occupancy 1 ->
// all blocks co-resident in wave 1. Counters are monotonic (each replay adds
// exactly GRID per barrier), so no reset is needed and replays are deterministic.
__device__ __forceinline__ void gbar(int i) {
    __threadfence();
    __syncthreads();
    if (threadIdx.x == 0) {
        unsigned int old = atomicAdd(&g_barc[i], 1u);
        unsigned int target = (old & ~(unsigned int)(GRID - 1)) + (unsigned int)GRID;
        while (atomicAdd(&g_barc[i], 0u) < target) { __nanosleep(64); }
        __threadfence();
    }
    __syncthreads();
}

__global__ void __launch_bounds__(TPB, 1) k_fused(
    const float* __restrict__ data, const float* __restrict__ c,
    const float* __restrict__ tv,   const float* __restrict__ x0_noise,
    const float* __restrict__ noise_bank,
    const float* __restrict__ W1,   const float* __restrict__ Wc,
    const float* __restrict__ Wt,   const float* __restrict__ b1,
    const float* __restrict__ W2,   float* __restrict__ out) {

    // 32.8 KB shared, reused across phases
    __shared__ __align__(16) float smem_raw[(Nn * 2 + 4) * 4];
    __shared__ float sred[TPB];
    float4* sdata = (float4*)smem_raw;       // phase 1: data[b] padded
    float*  sW1   = smem_raw;                // phase 3 aliases
    float*  sW2   = smem_raw + Dn * Hn;
    float*  sbase = smem_raw + 2 * Dn * Hn;

    const int t   = threadIdx.x;
    const int bid = blockIdx.x;
    const int gid = bid * TPB + t;

    // ---------------- phase 0: zero counters, init x0, cc = c @ Wc --------
    if (gid <= MAXIT) g_cnt[gid] = 0;
    for (int i = gid; i < NROWS * Dn; i += GRID * TPB) {
        int d = i & (Dn - 1);
        g_x0[i] = (d < NCOND) ? data[i] : x0_noise[i];
    }
    if (gid < Bn * Hn) {
        int bb = gid >> 8, h = gid & (Hn - 1);
        float acc = 0.f;
        #pragma unroll 8
        for (int j = 0; j < Cn; j++)
            acc = fmaf(c[bb * Cn + j], Wc[j * Hn + h], acc);
        g_cc[gid] = acc;
    }
    gbar(0);

    // ---------------- phase 1: full mismatch over all rows ----------------
    // block -> (b, tile): 128 rows per block, 4-way m-split per row.
    const int b    = bid >> 3;
    const int tile = bid & 7;
    {
        const float4* dptr = (const float4*)(data + (size_t)b * Nn * Dn);
        for (int i = t; i < Nn * 2; i += TPB)
            sdata[i + ((i >> 1) >> 8)] = dptr[i];   // pad: +1 float4 per 256 rows
        __syncthreads();

        const int q   = t & 3;
        const int r   = t >> 2;               // 0..127
        const int row = tile * 128 + r;
        const int rf  = b * Nn + row;

        const float4* xr = (const float4*)(g_x0 + (size_t)rf * Dn);
        const float4 xa = xr[0];
        const float4 xb = xr[1];

        float best = 3.402823466e38f;
        int bidx = -1;
        const int m0 = q * 256;
        #pragma unroll 4
        for (int m = m0; m < m0 + 256; m++) {
            int idx = 2 * m + q;              // pad term (m>>8)==q in this range
            float4 da = sdata[idx];
            float4 db = sdata[idx + 1];
            // sequential accumulation d = 0..7 (reference reduction order)
            float t0 = xa.x - da.x; float acc = t0 * t0;
            t0 = xa.y - da.y; acc = fmaf(t0, t0, acc);
            t0 = xa.z - da.z; acc = fmaf(t0, t0, acc);
            t0 = xa.w - da.w; acc = fmaf(t0, t0, acc);
            t0 = xb.x - db.x; acc = fmaf(t0, t0, acc);
            t0 = xb.y - db.y; acc = fmaf(t0, t0, acc);
            t0 = xb.z - db.z; acc = fmaf(t0, t0, acc);
            t0 = xb.w - db.w; acc = fmaf(t0, t0, acc);
            if (acc < best) { best = acc; bidx = m; }   // strict < -> first index
        }
        // merge the 4 m-quarters (lanes 4r..4r+3); tie -> lower m (first index)
        #pragma unroll
        for (int off = 2; off >= 1; off >>= 1) {
            float ob = __shfl_down_sync(0xffffffffu, best, off, 4);
            int   oi = __shfl_down_sync(0xffffffffu, bidx, off, 4);
            if (ob < best || (ob == best && oi < bidx)) { best = ob; bidx = oi; }
        }
        if (q == 0 && bidx != row) {
            int s = atomicAdd(&g_cnt[0], 1);
            g_lists[0][s] = rf;
        }
    }
    gbar(1);

    // ---------------- phase 2: iterative renoise (row-local) --------------
    // Unmasked rows are invariant (x and data unchanged => argmin unchanged),
    // so only listed rows are renoised + rechecked. One row per warp.
    for (int it = 0; it < MAXIT; it++) {
        const int cnt = g_cnt[it];
        if (cnt >= 10) {                        // while-loop condition
            const int* src = g_lists[it & 1];
            int*       dst = g_lists[(it + 1) & 1];
            const int lane = t & 31;
            const int gw   = gid >> 5;          // global warp id, 0..2047
            for (int w = gw; w < cnt; w += (GRID * TPB) / 32) {
                const int rf = src[w];
                const int b2 = rf >> 10;
                const int n  = rf & (Nn - 1);
                // replace free dims with this iteration's noise
                if (lane >= NCOND && lane < Dn)
                    g_x0[(size_t)rf * Dn + lane] =
                        noise_bank[((size_t)it * NROWS + rf) * Dn + lane];
                __threadfence_block();
                __syncwarp();
                const float4* xr = (const float4*)(g_x0 + (size_t)rf * Dn);
                const float4 xa = xr[0];
                const float4 xb = xr[1];
                const float4* dp = (const float4*)(data + (size_t)b2 * Nn * Dn);

                float best = 3.402823466e38f;
                int bi = -1;
                #pragma unroll 4
                for (int m = lane; m < Nn; m += 32) {
                    float4 da = dp[2 * m];
                    float4 db = dp[2 * m + 1];
                    float t0 = xa.x - da.x; float acc = t0 * t0;
                    t0 = xa.y - da.y; acc = fmaf(t0, t0, acc);
                    t0 = xa.z - da.z; acc = fmaf(t0, t0, acc);
                    t0 = xa.w - da.w; acc = fmaf(t0, t0, acc);
                    t0 = xb.x - db.x; acc = fmaf(t0, t0, acc);
                    t0 = xb.y - db.y; acc = fmaf(t0, t0, acc);
                    t0 = xb.z - db.z; acc = fmaf(t0, t0, acc);
                    t0 = xb.w - db.w; acc = fmaf(t0, t0, acc);
                    if (acc < best) { best = acc; bi = m; }
                }
                // warp argmin; tie -> lower m (first index)
                #pragma unroll
                for (int off = 16; off >= 1; off >>= 1) {
                    float ob = __shfl_down_sync(0xffffffffu, best, off);
                    int   oi = __shfl_down_sync(0xffffffffu, bi, off);
                    if (ob < best || (ob == best && oi < bi)) { best = ob; bi = oi; }
                }
                if (lane == 0 && bi != n) {
                    int s = atomicAdd(&g_cnt[it + 1], 1);
                    dst[s] = rf;
                }
            }
        }
        gbar(2 + it);
    }

    // ---------------- phase 3: fused model + masked loss ------------------
    {
        for (int i = t; i < Dn * Hn; i += TPB) sW1[i] = W1[i];
        for (int i = t; i < Hn * Dn; i += TPB) sW2[i] = W2[i];
        const float tb = tv[b];
        for (int h = t; h < Hn; h += TPB)
            sbase[h] = g_cc[b * Hn + h] + tb * Wt[h] + b1[h];
        __syncthreads();

        const int q   = t & 3;
        const int r   = t >> 2;
        const int row = tile * 128 + r;
        const int base = (b * Nn + row) * Dn;

        float xt[Dn], ut[Dn], vt[Dn];
        #pragma unroll
        for (int d = 0; d < Dn; d++) {
            float dv = data[base + d];
            float xv = g_x0[base + d];
            ut[d] = dv - xv;
            xt[d] = (d < NCOND) ? dv : ((1.0f - tb) * xv + tb * dv);
            vt[d] = 0.f;
        }
        const int h0 = q * (Hn / 4);
        for (int h = h0; h < h0 + Hn / 4; h++) {
            float pre = sbase[h];
            #pragma unroll
            for (int d = 0; d < Dn; d++) pre = fmaf(xt[d], sW1[d * Hn + h], pre);
            float hh = tanhf(pre);
            #pragma unroll
            for (int d = 0; d < Dn; d++) vt[d] = fmaf(hh, sW2[h * Dn + d], vt[d]);
        }
        // merge h-quarters (lanes 4r..4r+3)
        #pragma unroll
        for (int off = 2; off >= 1; off >>= 1) {
            #pragma unroll
            for (int d = 0; d < Dn; d++)
                vt[d] += __shfl_down_sync(0xffffffffu, vt[d], off, 4);
        }
        float part = 0.f;
        if (q == 0) {
            #pragma unroll
            for (int d = NCOND; d < Dn; d++) {
                float e = vt[d] - ut[d];
                part = fmaf(e, e, part);
            }
        }
        sred[t] = part;
        __syncthreads();
        // deterministic tree reduction
        for (int s = TPB / 2; s > 0; s >>= 1) {
            if (t < s) sred[t] += sred[t + s];
            __syncthreads();
        }
        if (t == 0) g_partial[bid] = sred[0];
    }
    gbar(6);

    // ---------------- phase 4: per-batch deterministic sum ----------------
    if (bid == 0 && t < Bn) {
        float s = 0.f;
        #pragma unroll
        for (int i = 0; i < 8; i++) s += g_partial[t * 8 + i];
        out[t] = s / (float)(Nn * (Dn - NCOND));
    }
}

// ---------------- launch: ONE graph node ----------------------------------
extern "C" void kernel_launch(void* const* d_in, const int* in_sizes, int n_in,
                              void* d_out, int out_size) {
    const float* data = (const float*)d_in[0];
    const float* c    = (const float*)d_in[1];
    const float* t    = (const float*)d_in[2];
    const float* x0n  = (const float*)d_in[3];
    const float* nb   = (const float*)d_in[4];
    const float* W1   = (const float*)d_in[5];
    const float* Wc   = (const float*)d_in[6];
    const float* Wt   = (const float*)d_in[7];
    const float* b1   = (const float*)d_in[8];
    const float* W2   = (const float*)d_in[9];
    float* out = (float*)d_out;

    k_fused<<<GRID, TPB>>>(data, c, t, x0n, nb, W1, Wc, Wt, b1, W2, out);
}

// round 6
// speedup vs baseline: 3.3292x; 1.8687x over previous
#include <cuda_runtime.h>

#define Bn 16
#define Nn 1024
#define Dn 8
#define Cn 128
#define Hn 256
#define NCOND 3
#define MAXIT 4
#define NROWS (Bn * Nn)
#define GRID 128
#define TPB 512
#define FLT_BIG 3.402823466e38f

// ---------------- device scratch (no allocations allowed) ----------------
__device__ __align__(16) float g_x0[NROWS * Dn];   // 512 KB
__device__ float g_cc[Bn * Hn];
__device__ int g_cnt[MAXIT + 1][Bn];               // per-(pass, batch) masked count
__device__ int g_lists[2][Bn][Nn];                 // ping-pong per-batch masked row lists
__device__ float g_partial[GRID];
__device__ unsigned int g_barc[8];                 // monotonic barrier counters (never reset)

// Software grid barrier. GRID=128 blocks <= 148 SMs at occupancy 1 -> all
// co-resident; monotonic counters need no reset and are replay-deterministic.
__device__ __forceinline__ void gbar(int i) {
    __threadfence();
    __syncthreads();
    if (threadIdx.x == 0) {
        unsigned int old = atomicAdd(&g_barc[i], 1u);
        unsigned int target = (old & ~(unsigned int)(GRID - 1)) + (unsigned int)GRID;
        while (atomicAdd(&g_barc[i], 0u) < target) { __nanosleep(32); }
        __threadfence();
    }
    __syncthreads();
}

// squared distance, sequential d0..d7 accumulation (reference reduction order)
__device__ __forceinline__ float dist8(const float4 xa, const float4 xb,
                                       const float4 da, const float4 db) {
    float t0 = xa.x - da.x; float acc = t0 * t0;
    t0 = xa.y - da.y; acc = fmaf(t0, t0, acc);
    t0 = xa.z - da.z; acc = fmaf(t0, t0, acc);
    t0 = xa.w - da.w; acc = fmaf(t0, t0, acc);
    t0 = xb.x - db.x; acc = fmaf(t0, t0, acc);
    t0 = xb.y - db.y; acc = fmaf(t0, t0, acc);
    t0 = xb.z - db.z; acc = fmaf(t0, t0, acc);
    t0 = xb.w - db.w; acc = fmaf(t0, t0, acc);
    return acc;
}

// smem float4 index for data row m, half h (pad 1 float4 per 64 rows:
// lane sub-ranges land on distinct bank quads within each LDS phase-octet)
#define SIDX(m) (2 * (m) + ((m) >> 6))

__global__ void __launch_bounds__(TPB, 1) k_fused(
    const float* __restrict__ data, const float* __restrict__ c,
    const float* __restrict__ tv,   const float* __restrict__ x0_noise,
    const float* __restrict__ noise_bank,
    const float* __restrict__ W1,   const float* __restrict__ Wc,
    const float* __restrict__ Wt,   const float* __restrict__ b1,
    const float* __restrict__ W2,   float* __restrict__ out) {

    // 33 KB tile (persists through phases 1-2), aliased by weights in phase 3
    __shared__ __align__(16) float smem_raw[(Nn * 2 + 16) * 4];
    __shared__ float sred[TPB];
    float4* sdata = (float4*)smem_raw;
    float*  sW1   = smem_raw;
    float*  sW2   = smem_raw + Dn * Hn;
    float*  sbase = smem_raw + 2 * Dn * Hn;

    const int t   = threadIdx.x;
    const int bid = blockIdx.x;
    const int gid = bid * TPB + t;
    const int b    = bid >> 3;           // batch owned by this block
    const int tile = bid & 7;

    // ---------------- phase 0: zero counters, init x0, cc = c @ Wc --------
    if (gid < (MAXIT + 1) * Bn) ((int*)g_cnt)[gid] = 0;
    for (int i = gid; i < NROWS * Dn; i += GRID * TPB) {
        int d = i & (Dn - 1);
        g_x0[i] = (d < NCOND) ? data[i] : x0_noise[i];
    }
    if (gid < Bn * Hn) {
        int bb = gid >> 8, h = gid & (Hn - 1);
        float acc = 0.f;
        #pragma unroll 8
        for (int j = 0; j < Cn; j++)
            acc = fmaf(c[bb * Cn + j], Wc[j * Hn + h], acc);
        g_cc[gid] = acc;
    }
    gbar(0);

    // ---------------- load data[b] tile into smem (padded) ----------------
    {
        const float4* dptr = (const float4*)(data + (size_t)b * Nn * Dn);
        for (int i = t; i < Nn * 2; i += TPB) {
            int m = i >> 1;
            sdata[SIDX(m) + (i & 1)] = dptr[i];
        }
        __syncthreads();
    }

    const int sub  = t & 15;             // m-sixteenth: [sub*64, sub*64+64)
    const int quad = t >> 4;             // 0..31: 4-row group within 128-row tile
    const int sbase16 = 129 * sub;       // SIDX(sub*64)

    // ---------------- phase 1: full mismatch, R=4 rows per thread ---------
    {
        float4 xa[4], xb[4];
        int rown[4];
        #pragma unroll
        for (int j = 0; j < 4; j++) {
            rown[j] = tile * 128 + quad * 4 + j;
            const float4* xr = (const float4*)(g_x0 + ((size_t)b * Nn + rown[j]) * Dn);
            xa[j] = xr[0]; xb[j] = xr[1];
        }
        float best[4] = {FLT_BIG, FLT_BIG, FLT_BIG, FLT_BIG};
        int bidx[4] = {-1, -1, -1, -1};
        #pragma unroll 4
        for (int i = 0; i < 64; i++) {
            float4 da = sdata[sbase16 + 2 * i];
            float4 db = sdata[sbase16 + 2 * i + 1];
            int m = sub * 64 + i;
            #pragma unroll
            for (int j = 0; j < 4; j++) {
                float acc = dist8(xa[j], xb[j], da, db);
                if (acc < best[j]) { best[j] = acc; bidx[j] = m; }  // strict <
            }
        }
        // merge the 16 m-sixteenths (width-16 shuffle); tie -> lower m
        #pragma unroll
        for (int off = 8; off >= 1; off >>= 1) {
            #pragma unroll
            for (int j = 0; j < 4; j++) {
                float ob = __shfl_down_sync(0xffffffffu, best[j], off, 16);
                int   oi = __shfl_down_sync(0xffffffffu, bidx[j], off, 16);
                if (ob < best[j] || (ob == best[j] && oi < bidx[j])) {
                    best[j] = ob; bidx[j] = oi;
                }
            }
        }
        if (sub == 0) {
            int nm = 0, mr[4];
            #pragma unroll
            for (int j = 0; j < 4; j++)
                if (bidx[j] != rown[j]) mr[nm++] = rown[j];
            if (nm) {
                int s = atomicAdd(&g_cnt[0][b], nm);
                for (int k = 0; k < nm; k++) g_lists[0][b][s + k] = mr[k];
            }
        }
    }
    gbar(1);

    // ---------------- phase 2: iterative renoise (smem tile reuse) --------
    // Unmasked rows invariant => only listed rows renoised + rechecked.
    const int wid = t >> 5;
    const int l   = t & 31;
    const int qd  = l >> 4;              // 0/1: which 4-row group in this warp
    const int wb  = (bid & 7) * 16 + wid;  // warp index within batch: 0..127
    for (int it = 0; it < MAXIT; it++) {
        int total = 0;
        #pragma unroll
        for (int i = 0; i < Bn; i++) total += g_cnt[it][i];
        if (total >= 10) {               // while-loop condition (global mask sum)
            const int cnt = g_cnt[it][b];
            const int* src = g_lists[it & 1][b];
            int*       dst = g_lists[(it + 1) & 1][b];
            const int ng = (cnt + 7) >> 3;          // 8 rows per warp-pass
            for (int g = wb; g < ng; g += 128) {
                int rn[4]; bool val[4];
                float4 xa[4], xb[4];
                #pragma unroll
                for (int j = 0; j < 4; j++) {
                    int li = g * 8 + qd * 4 + j;
                    val[j] = li < cnt;
                    rn[j] = val[j] ? src[li] : 0;
                    int rf = b * Nn + rn[j];
                    // x row = [data dims 0-2, noise_bank[it] dims 3-7]
                    float4 dA = ((const float4*)data)[(size_t)rf * 2];
                    const float4* np =
                        (const float4*)(noise_bank + ((size_t)it * NROWS + rf) * Dn);
                    float4 nA = np[0], nB = np[1];
                    xa[j] = make_float4(dA.x, dA.y, dA.z, nA.w);
                    xb[j] = nB;
                    if (sub == 0 && val[j]) {       // persist renoise for phase 3
                        g_x0[(size_t)rf * Dn + 3] = nA.w;
                        *((float4*)(g_x0 + (size_t)rf * Dn + 4)) = nB;
                    }
                }
                float best[4] = {FLT_BIG, FLT_BIG, FLT_BIG, FLT_BIG};
                int bidx[4] = {-1, -1, -1, -1};
                #pragma unroll 4
                for (int i = 0; i < 64; i++) {
                    float4 da = sdata[sbase16 + 2 * i];
                    float4 db = sdata[sbase16 + 2 * i + 1];
                    int m = sub * 64 + i;
                    #pragma unroll
                    for (int j = 0; j < 4; j++) {
                        float acc = dist8(xa[j], xb[j], da, db);
                        if (acc < best[j]) { best[j] = acc; bidx[j] = m; }
                    }
                }
                #pragma unroll
                for (int off = 8; off >= 1; off >>= 1) {
                    #pragma unroll
                    for (int j = 0; j < 4; j++) {
                        float ob = __shfl_down_sync(0xffffffffu, best[j], off, 16);
                        int   oi = __shfl_down_sync(0xffffffffu, bidx[j], off, 16);
                        if (ob < best[j] || (ob == best[j] && oi < bidx[j])) {
                            best[j] = ob; bidx[j] = oi;
                        }
                    }
                }
                if (sub == 0) {
                    int nm = 0, mr[4];
                    #pragma unroll
                    for (int j = 0; j < 4; j++)
                        if (val[j] && bidx[j] != rn[j]) mr[nm++] = rn[j];
                    if (nm) {
                        int s = atomicAdd(&g_cnt[it + 1][b], nm);
                        for (int k = 0; k < nm; k++) dst[s + k] = mr[k];
                    }
                }
            }
        }
        gbar(2 + it);
    }

    // ---------------- phase 3: fused model + masked loss ------------------
    {
        for (int i = t; i < Dn * Hn; i += TPB) sW1[i] = W1[i];
        for (int i = t; i < Hn * Dn; i += TPB) sW2[i] = W2[i];
        const float tb = tv[b];
        for (int h = t; h < Hn; h += TPB)
            sbase[h] = g_cc[b * Hn + h] + tb * Wt[h] + b1[h];
        __syncthreads();

        const int q   = t & 3;
        const int r   = t >> 2;
        const int row = tile * 128 + r;
        const int base = (b * Nn + row) * Dn;

        float xt[Dn], ut[Dn], vt[Dn];
        #pragma unroll
        for (int d = 0; d < Dn; d++) {
            float dv = data[base + d];
            float xv = g_x0[base + d];
            ut[d] = dv - xv;
            xt[d] = (d < NCOND) ? dv : ((1.0f - tb) * xv + tb * dv);
            vt[d] = 0.f;
        }
        const int h0 = q * (Hn / 4);
        for (int h = h0; h < h0 + Hn / 4; h++) {
            float pre = sbase[h];
            #pragma unroll
            for (int d = 0; d < Dn; d++) pre = fmaf(xt[d], sW1[d * Hn + h], pre);
            float hh = tanhf(pre);
            #pragma unroll
            for (int d = 0; d < Dn; d++) vt[d] = fmaf(hh, sW2[h * Dn + d], vt[d]);
        }
        #pragma unroll
        for (int off = 2; off >= 1; off >>= 1) {
            #pragma unroll
            for (int d = 0; d < Dn; d++)
                vt[d] += __shfl_down_sync(0xffffffffu, vt[d], off, 4);
        }
        float part = 0.f;
        if (q == 0) {
            #pragma unroll
            for (int d = NCOND; d < Dn; d++) {
                float e = vt[d] - ut[d];
                part = fmaf(e, e, part);
            }
        }
        sred[t] = part;
        __syncthreads();
        for (int s = TPB / 2; s > 0; s >>= 1) {
            if (t < s) sred[t] += sred[t + s];
            __syncthreads();
        }
        if (t == 0) g_partial[bid] = sred[0];
    }
    gbar(6);

    // ---------------- phase 4: per-batch deterministic sum ----------------
    if (bid == 0 && t < Bn) {
        float s = 0.f;
        #pragma unroll
        for (int i = 0; i < 8; i++) s += g_partial[t * 8 + i];
        out[t] = s / (float)(Nn * (Dn - NCOND));
    }
}

// ---------------- launch: ONE graph node ----------------------------------
extern "C" void kernel_launch(void* const* d_in, const int* in_sizes, int n_in,
                              void* d_out, int out_size) {
    const float* data = (const float*)d_in[0];
    const float* c    = (const float*)d_in[1];
    const float* t    = (const float*)d_in[2];
    const float* x0n  = (const float*)d_in[3];
    const float* nb   = (const float*)d_in[4];
    const float* W1   = (const float*)d_in[5];
    const float* Wc   = (const float*)d_in[6];
    const float* Wt   = (const float*)d_in[7];
    const float* b1   = (const float*)d_in[8];
    const float* W2   = (const float*)d_in[9];
    float* out = (float*)d_out;

    k_fused<<<GRID, TPB>>>(data, c, t, x0n, nb, W1, Wc, Wt, b1, W2, out);
}